// round 1
// baseline (speedup 1.0000x reference)
#include <cuda_runtime.h>
#include <cuda_bf16.h>

// Problem: B=4, Lp=Lq=256, D=256, H=256.
// Inputs (metadata order): Hp, Hq, Wc1, Wc2, vc, Wb, Wd, vd, Wm, vm (all fp32)
// Output: concat(qc, qb, qd, qm), each (B, Lp, D) fp32.

#define BB 4
#define LL 256
#define DD 256
#define HH 256

// -------- scratch (static device globals; no allocation allowed) --------
__device__ float g_S1[BB * LL * HH];  // Hq @ Wc1
__device__ float g_S2[BB * LL * HH];  // Hp @ Wc2
__device__ float g_G [BB * LL * HH];  // Hq @ Wb
__device__ float g_M1[BB * LL * HH];  // Hq @ Wm
__device__ float g_M2[BB * LL * HH];  // Hp @ Wm

// -------- helpers --------
__device__ __forceinline__ float tanh_fast(float x) {
    float y;
    asm("tanh.approx.f32 %0, %1;" : "=f"(y) : "f"(x));
    return y;
}

__device__ __forceinline__ unsigned long long pack_dup(float a) {
    unsigned long long r;
    asm("mov.b64 %0, {%1, %1};" : "=l"(r) : "f"(a));
    return r;
}

__device__ __forceinline__ void unpack2(unsigned long long v, float& lo, float& hi) {
    asm("mov.b64 {%0, %1}, %2;" : "=f"(lo), "=f"(hi) : "l"(v));
}

__device__ __forceinline__ void ffma2(unsigned long long& d, unsigned long long a,
                                      unsigned long long b) {
    asm("fma.rn.f32x2 %0, %1, %2, %0;" : "+l"(d) : "l"(a), "l"(b));
}

// block-wide reduce (256 threads). is_max=true -> max, else sum. Broadcast result.
__device__ __forceinline__ float block_reduce(float v, bool is_max, float* rbuf,
                                              int lane, int wrp) {
    #pragma unroll
    for (int o = 16; o; o >>= 1) {
        float u = __shfl_xor_sync(0xffffffffu, v, o);
        v = is_max ? fmaxf(v, u) : (v + u);
    }
    if (lane == 0) rbuf[wrp] = v;
    __syncthreads();
    if (threadIdx.x == 0) {
        float r = rbuf[0];
        #pragma unroll
        for (int i = 1; i < 8; ++i) r = is_max ? fmaxf(r, rbuf[i]) : (r + rbuf[i]);
        rbuf[0] = r;
    }
    __syncthreads();
    float r = rbuf[0];
    __syncthreads();  // rbuf safe to reuse after return
    return r;
}

// -------- kernel 1: 5 projection GEMMs (M=1024, N=256, K=256) --------
// C[m][n] = sum_k A[m][k] * W[k][n]
__global__ void proj_kernel(const float* __restrict__ Hp, const float* __restrict__ Hq,
                            const float* __restrict__ Wc1, const float* __restrict__ Wc2,
                            const float* __restrict__ Wb,  const float* __restrict__ Wm) {
    const float* A; const float* W; float* C;
    switch (blockIdx.z) {
        case 0:  A = Hq; W = Wc1; C = g_S1; break;
        case 1:  A = Hp; W = Wc2; C = g_S2; break;
        case 2:  A = Hq; W = Wb;  C = g_G;  break;
        case 3:  A = Hq; W = Wm;  C = g_M1; break;
        default: A = Hp; W = Wm;  C = g_M2; break;
    }
    const int mb = blockIdx.x * 64, nb = blockIdx.y * 64;
    const int tid = threadIdx.x, ty = tid >> 4, tx = tid & 15;

    __shared__ float As[16][68];  // [k][m], pad 68 (16B-aligned rows)
    __shared__ float Bs[16][68];  // [k][n]

    float acc[4][4] = {};
    for (int kt = 0; kt < 16; ++kt) {
        {   // A tile 64x16, store transposed
            int m = tid >> 2, k4 = (tid & 3) * 4;
            float4 v = *reinterpret_cast<const float4*>(&A[(mb + m) * 256 + kt * 16 + k4]);
            As[k4 + 0][m] = v.x; As[k4 + 1][m] = v.y;
            As[k4 + 2][m] = v.z; As[k4 + 3][m] = v.w;
        }
        {   // B tile 16x64
            int k = tid >> 4, n4 = (tid & 15) * 4;
            float4 v = *reinterpret_cast<const float4*>(&W[(kt * 16 + k) * 256 + nb + n4]);
            *reinterpret_cast<float4*>(&Bs[k][n4]) = v;
        }
        __syncthreads();
        #pragma unroll
        for (int k = 0; k < 16; ++k) {
            float a[4], bv[4];
            #pragma unroll
            for (int i = 0; i < 4; ++i) a[i] = As[k][ty + 16 * i];
            #pragma unroll
            for (int j = 0; j < 4; ++j) bv[j] = Bs[k][tx + 16 * j];
            #pragma unroll
            for (int i = 0; i < 4; ++i)
                #pragma unroll
                for (int j = 0; j < 4; ++j) acc[i][j] = fmaf(a[i], bv[j], acc[i][j]);
        }
        __syncthreads();
    }
    #pragma unroll
    for (int i = 0; i < 4; ++i)
        #pragma unroll
        for (int j = 0; j < 4; ++j)
            C[(mb + ty + 16 * i) * 256 + nb + tx + 16 * j] = acc[i][j];
}

// -------- kernel 2: fused per-(b,p) scores + softmax + attend --------
__global__ __launch_bounds__(256)
void fused_kernel(const float* __restrict__ Hp, const float* __restrict__ Hq,
                  const float* __restrict__ Wd,
                  const float* __restrict__ vc, const float* __restrict__ vd,
                  const float* __restrict__ vm, float* __restrict__ out) {
    const int p = blockIdx.x, b = blockIdx.y;
    const int tid = threadIdx.x;
    const int lane = tid & 31, wrp = tid >> 5;
    const int ty = tid >> 4, tx = tid & 15;

    __shared__ float hp[DD], s2r[HH], m2r[HH];
    __shared__ float vcs[HH], vds[HH], vms[HH];
    __shared__ float sc_s[LL], sb_s[LL], sd_s[LL], sm_s[LL];
    __shared__ float As[64][17];    // q x k tile of (Hq .* hp)
    __shared__ float Bs[16][256];   // k x h tile of Wd
    __shared__ float red[64][17];
    __shared__ float rbuf[8];

    // ---- stage 0: per-(b,p) rows + vectors into smem ----
    hp [tid] = Hp  [(b * LL + p) * DD + tid];
    s2r[tid] = g_S2[(b * LL + p) * HH + tid];
    m2r[tid] = g_M2[(b * LL + p) * HH + tid];
    vcs[tid] = vc[tid]; vds[tid] = vd[tid]; vms[tid] = vm[tid];
    __syncthreads();

    // ---- stage 1: branches c, m, b scores (warp per q, lanes over h) ----
    for (int qi = 0; qi < 32; ++qi) {
        int q = wrp * 32 + qi;
        const float* s1row = &g_S1[(b * LL + q) * HH];
        const float* m1row = &g_M1[(b * LL + q) * HH];
        const float* grow  = &g_G [(b * LL + q) * HH];
        float ac = 0.f, am = 0.f, ab = 0.f;
        #pragma unroll
        for (int it = 0; it < 8; ++it) {
            int h = lane + 32 * it;
            ac = fmaf(tanh_fast(s1row[h] + s2r[h]), vcs[h], ac);
            am = fmaf(tanh_fast(m1row[h] - m2r[h]), vms[h], am);
            ab = fmaf(hp[h], grow[h], ab);
        }
        #pragma unroll
        for (int o = 16; o; o >>= 1) {
            ac += __shfl_xor_sync(0xffffffffu, ac, o);
            am += __shfl_xor_sync(0xffffffffu, am, o);
            ab += __shfl_xor_sync(0xffffffffu, ab, o);
        }
        if (lane == 0) { sc_s[q] = ac; sm_s[q] = am; sb_s[q] = ab; }
    }

    // ---- stage 2: branch d — per-(b,p) GEMM T = (Hq .* hp) @ Wd, fused tanh*vd ----
    // q in chunks of 64; thread (ty,tx): rows qbase+ty*4+i (i<4), h pairs 2*tx+32*j (j<8)
    for (int qc = 0; qc < 4; ++qc) {
        unsigned long long acc[4][8];
        #pragma unroll
        for (int i = 0; i < 4; ++i)
            #pragma unroll
            for (int j = 0; j < 8; ++j) acc[i][j] = 0ull;

        for (int kt = 0; kt < 16; ++kt) {
            __syncthreads();  // WAR on As/Bs (and red reads of prev qc)
            {   // As: 64 q x 16 k, scaled by hp
                int q = tid >> 2, k4 = (tid & 3) * 4;
                int kb = kt * 16 + k4;
                float4 v = *reinterpret_cast<const float4*>(
                    &Hq[(b * LL + qc * 64 + q) * DD + kb]);
                As[q][k4 + 0] = v.x * hp[kb + 0];
                As[q][k4 + 1] = v.y * hp[kb + 1];
                As[q][k4 + 2] = v.z * hp[kb + 2];
                As[q][k4 + 3] = v.w * hp[kb + 3];
            }
            {   // Bs: 16 k x 256 h of Wd
                int kr = tid >> 4, h0 = (tid & 15) * 16;
                #pragma unroll
                for (int v4 = 0; v4 < 4; ++v4) {
                    float4 w = *reinterpret_cast<const float4*>(
                        &Wd[(kt * 16 + kr) * HH + h0 + 4 * v4]);
                    *reinterpret_cast<float4*>(&Bs[kr][h0 + 4 * v4]) = w;
                }
            }
            __syncthreads();
            #pragma unroll
            for (int k = 0; k < 16; ++k) {
                unsigned long long aa[4];
                #pragma unroll
                for (int i = 0; i < 4; ++i) aa[i] = pack_dup(As[ty * 4 + i][k]);
                #pragma unroll
                for (int j = 0; j < 8; ++j) {
                    unsigned long long bv = *reinterpret_cast<const unsigned long long*>(
                        &Bs[k][2 * tx + 32 * j]);
                    #pragma unroll
                    for (int i = 0; i < 4; ++i) ffma2(acc[i][j], aa[i], bv);
                }
            }
        }
        // tanh + dot with vd (partial over this thread's 16 h)
        float part[4] = {0.f, 0.f, 0.f, 0.f};
        #pragma unroll
        for (int i = 0; i < 4; ++i)
            #pragma unroll
            for (int j = 0; j < 8; ++j) {
                float lo, hi;
                unpack2(acc[i][j], lo, hi);
                int h = 2 * tx + 32 * j;
                part[i] = fmaf(tanh_fast(lo), vds[h],     part[i]);
                part[i] = fmaf(tanh_fast(hi), vds[h + 1], part[i]);
            }
        __syncthreads();  // red WAR
        #pragma unroll
        for (int i = 0; i < 4; ++i) red[ty * 4 + i][tx] = part[i];
        __syncthreads();
        if (tid < 64) {
            float s = 0.f;
            #pragma unroll
            for (int c = 0; c < 16; ++c) s += red[tid][c];
            sd_s[qc * 64 + tid] = s;
        }
    }
    __syncthreads();

    // ---- stage 3: softmax over q for each branch (weights overwrite scores) ----
    float* sarr[4] = {sc_s, sb_s, sd_s, sm_s};
    #pragma unroll
    for (int br = 0; br < 4; ++br) {
        float v = sarr[br][tid];
        __syncthreads();
        float mx  = block_reduce(v, true,  rbuf, lane, wrp);
        float e   = __expf(v - mx);
        float sum = block_reduce(e, false, rbuf, lane, wrp);
        sarr[br][tid] = e / sum;
    }
    __syncthreads();

    // ---- stage 4: attend — out[d] = sum_q w[q] * Hq[b,q,d], shared Hq loads ----
    float oc = 0.f, ob = 0.f, od = 0.f, om = 0.f;
    const float* hqb = &Hq[(b * LL) * DD + tid];
    for (int q = 0; q < LL; ++q) {
        float hq = hqb[q * DD];
        oc = fmaf(sc_s[q], hq, oc);
        ob = fmaf(sb_s[q], hq, ob);
        od = fmaf(sd_s[q], hq, od);
        om = fmaf(sm_s[q], hq, om);
    }
    const int base = (b * LL + p) * DD + tid;
    const int BR = BB * LL * DD;
    out[0 * BR + base] = oc;
    out[1 * BR + base] = ob;
    out[2 * BR + base] = od;
    out[3 * BR + base] = om;
}

extern "C" void kernel_launch(void* const* d_in, const int* in_sizes, int n_in,
                              void* d_out, int out_size) {
    (void)in_sizes; (void)n_in; (void)out_size;
    const float* Hp  = (const float*)d_in[0];
    const float* Hq  = (const float*)d_in[1];
    const float* Wc1 = (const float*)d_in[2];
    const float* Wc2 = (const float*)d_in[3];
    const float* vc  = (const float*)d_in[4];
    const float* Wb  = (const float*)d_in[5];
    const float* Wd  = (const float*)d_in[6];
    const float* vd  = (const float*)d_in[7];
    const float* Wm  = (const float*)d_in[8];
    const float* vm  = (const float*)d_in[9];
    float* out = (float*)d_out;

    dim3 gproj(16, 4, 5);                 // 1024/64 m-tiles, 256/64 n-tiles, 5 GEMMs
    proj_kernel<<<gproj, 256>>>(Hp, Hq, Wc1, Wc2, Wb, Wm);

    dim3 gfused(LL, BB);                  // one CTA per (p, b)
    fused_kernel<<<gfused, 256>>>(Hp, Hq, Wd, vc, vd, vm, out);
}

// round 3
// speedup vs baseline: 1.9634x; 1.9634x over previous
#include <cuda_runtime.h>
#include <cuda_bf16.h>
#include <cstdint>

// Problem: B=4, Lp=Lq=256, D=256, H=256.
// Inputs (metadata order): Hp, Hq, Wc1, Wc2, vc, Wb, Wd, vd, Wm, vm (all fp32)
// Output: concat(qc, qb, qd, qm), each (B, Lp, D) fp32.

#define BB 4
#define LL 256
#define DD 256
#define HH 256

// -------- scratch (static device globals; no allocation allowed) --------
__device__ float g_S1[BB * LL * HH];  // Hq @ Wc1
__device__ float g_S2[BB * LL * HH];  // Hp @ Wc2
__device__ float g_G [BB * LL * HH];  // Hq @ Wb
__device__ float g_M1[BB * LL * HH];  // Hq @ Wm
__device__ float g_M2[BB * LL * HH];  // Hp @ Wm
__device__ float g_SD[BB * LL * LL];  // branch-d raw scores [b][p][q]
__device__ __nv_bfloat16 g_Wdh[DD * HH];  // Wd split high [k][h]
__device__ __nv_bfloat16 g_Wdl[DD * HH];  // Wd split low  [k][h]

// ======================= helpers =======================
__device__ __forceinline__ uint32_t smem_u32(const void* p) {
    uint32_t a;
    asm("{ .reg .u64 t; cvta.to.shared.u64 t, %1; cvt.u32.u64 %0, t; }"
        : "=r"(a) : "l"(p));
    return a;
}

__device__ __forceinline__ float tanh_fast(float x) {
    float y;
    asm("tanh.approx.f32 %0, %1;" : "=f"(y) : "f"(x));
    return y;
}

#define SWZ128(off) ((off) ^ (((off) >> 3) & 0x70))

__device__ __forceinline__ void ldm_x4(uint32_t* r, uint32_t addr) {
    asm volatile("ldmatrix.sync.aligned.m8n8.x4.shared.b16 {%0,%1,%2,%3}, [%4];"
                 : "=r"(r[0]), "=r"(r[1]), "=r"(r[2]), "=r"(r[3]) : "r"(addr));
}

__device__ __forceinline__ void ldm_x4t(uint32_t* r, uint32_t addr) {
    asm volatile("ldmatrix.sync.aligned.m8n8.x4.trans.shared.b16 {%0,%1,%2,%3}, [%4];"
                 : "=r"(r[0]), "=r"(r[1]), "=r"(r[2]), "=r"(r[3]) : "r"(addr));
}

__device__ __forceinline__ void mma16816(float* d, const uint32_t* a, const uint32_t* b) {
    asm volatile(
        "mma.sync.aligned.m16n8k16.row.col.f32.bf16.bf16.f32 "
        "{%0,%1,%2,%3}, {%4,%5,%6,%7}, {%8,%9}, {%0,%1,%2,%3};"
        : "+f"(d[0]), "+f"(d[1]), "+f"(d[2]), "+f"(d[3])
        : "r"(a[0]), "r"(a[1]), "r"(a[2]), "r"(a[3]), "r"(b[0]), "r"(b[1]));
}

// ======================= kernel 0: split Wd into bf16 hi/lo =======================
__global__ void prep_wd_kernel(const float* __restrict__ Wd) {
    int k = blockIdx.x, h = threadIdx.x;
    float w = Wd[k * HH + h];
    __nv_bfloat16 hi = __float2bfloat16(w);
    g_Wdh[k * HH + h] = hi;
    g_Wdl[k * HH + h] = __float2bfloat16(w - __bfloat162float(hi));
}

// ======================= kernel 1: 5 projection GEMMs =======================
__global__ void proj_kernel(const float* __restrict__ Hp, const float* __restrict__ Hq,
                            const float* __restrict__ Wc1, const float* __restrict__ Wc2,
                            const float* __restrict__ Wb,  const float* __restrict__ Wm) {
    const float* A; const float* W; float* C;
    switch (blockIdx.z) {
        case 0:  A = Hq; W = Wc1; C = g_S1; break;
        case 1:  A = Hp; W = Wc2; C = g_S2; break;
        case 2:  A = Hq; W = Wb;  C = g_G;  break;
        case 3:  A = Hq; W = Wm;  C = g_M1; break;
        default: A = Hp; W = Wm;  C = g_M2; break;
    }
    const int mb = blockIdx.x * 64, nb = blockIdx.y * 64;
    const int tid = threadIdx.x, ty = tid >> 4, tx = tid & 15;

    __shared__ float As[16][68];
    __shared__ float Bs[16][68];

    float acc[4][4] = {};
    for (int kt = 0; kt < 16; ++kt) {
        {
            int m = tid >> 2, k4 = (tid & 3) * 4;
            float4 v = *reinterpret_cast<const float4*>(&A[(mb + m) * 256 + kt * 16 + k4]);
            As[k4 + 0][m] = v.x; As[k4 + 1][m] = v.y;
            As[k4 + 2][m] = v.z; As[k4 + 3][m] = v.w;
        }
        {
            int k = tid >> 4, n4 = (tid & 15) * 4;
            float4 v = *reinterpret_cast<const float4*>(&W[(kt * 16 + k) * 256 + nb + n4]);
            *reinterpret_cast<float4*>(&Bs[k][n4]) = v;
        }
        __syncthreads();
        #pragma unroll
        for (int k = 0; k < 16; ++k) {
            float a[4], bv[4];
            #pragma unroll
            for (int i = 0; i < 4; ++i) a[i] = As[k][ty + 16 * i];
            #pragma unroll
            for (int j = 0; j < 4; ++j) bv[j] = Bs[k][tx + 16 * j];
            #pragma unroll
            for (int i = 0; i < 4; ++i)
                #pragma unroll
                for (int j = 0; j < 4; ++j) acc[i][j] = fmaf(a[i], bv[j], acc[i][j]);
        }
        __syncthreads();
    }
    #pragma unroll
    for (int i = 0; i < 4; ++i)
        #pragma unroll
        for (int j = 0; j < 4; ++j)
            C[(mb + ty + 16 * i) * 256 + nb + tx + 16 * j] = acc[i][j];
}

// ======================= kernel 2: branch d via mma.sync (split bf16) =======================
// Per CTA = one (b,p):  T = (Hq .* hp) @ Wd  (256x256x256), fused tanh . vd.
// 3 passes: Ah*Bh + Ah*Bl + Al*Bh, fp32 accum. 8 warps: 2(q) x 4(h), warp tile 64x64.
static constexpr int OFF_AH  = 0;                 // 128 q x 128B (64 bf16)  16KB
static constexpr int OFF_AL  = 16384;
static constexpr int OFF_BH  = 32768;             // 4 panels x 64 k x 128B  32KB
static constexpr int OFF_BL  = 65536;
static constexpr int OFF_HP  = 98304;             // 256 f32
static constexpr int OFF_VD  = 99328;             // 256 f32
static constexpr int OFF_SDP = 100352;            // 256 f32
static constexpr int SMEM_D  = 101376;

__global__ __launch_bounds__(256, 1)
void branchd_kernel(const float* __restrict__ Hp, const float* __restrict__ Hq,
                    const float* __restrict__ vd) {
    extern __shared__ char dsm[];
    const uint32_t sb = smem_u32(dsm);
    const int p = blockIdx.x, b = blockIdx.y;
    const int tid = threadIdx.x, lane = tid & 31, warp = tid >> 5;
    const int wq = warp >> 2, wh = warp & 3;

    float* hp_s = reinterpret_cast<float*>(dsm + OFF_HP);
    float* vd_s = reinterpret_cast<float*>(dsm + OFF_VD);
    float* sdp  = reinterpret_cast<float*>(dsm + OFF_SDP);
    hp_s[tid] = Hp[(b * LL + p) * DD + tid];
    vd_s[tid] = vd[tid];
    sdp[tid] = 0.f;
    __syncthreads();

    // per-lane ldmatrix addressing components
    const int a_row = wq * 64 + (lane & 15);      // + m*16
    const int a_cb  = (lane >> 4) * 16;           // k-halfchunk byte
    const int b_kr  = ((lane >> 3) & 1) * 8 + (lane & 7);  // + k0
    const int b_hb  = (lane >> 4) * 16;           // h-halfchunk byte

    for (int qh = 0; qh < 2; ++qh) {
        float acc[4][8][4];
        #pragma unroll
        for (int m = 0; m < 4; ++m)
            #pragma unroll
            for (int n = 0; n < 8; ++n)
                #pragma unroll
                for (int e = 0; e < 4; ++e) acc[m][n][e] = 0.f;

        for (int kc = 0; kc < 4; ++kc) {
            __syncthreads();   // previous iter's frag reads done
            // ---- fill A hi/lo: rows q (128), cols k (64), SW128 ----
            #pragma unroll
            for (int t = 0; t < 8; ++t) {
                int i = tid + t * 256;            // 0..2047
                int row = i >> 4, c4 = i & 15;
                int kg = kc * 64 + c4 * 4;
                float4 v = *reinterpret_cast<const float4*>(
                    &Hq[(b * LL + qh * 128 + row) * DD + kg]);
                float a0 = v.x * hp_s[kg + 0];
                float a1 = v.y * hp_s[kg + 1];
                float a2 = v.z * hp_s[kg + 2];
                float a3 = v.w * hp_s[kg + 3];
                __nv_bfloat16 h0 = __float2bfloat16(a0), h1 = __float2bfloat16(a1);
                __nv_bfloat16 h2 = __float2bfloat16(a2), h3 = __float2bfloat16(a3);
                float l0f = a0 - __bfloat162float(h0);
                float l1f = a1 - __bfloat162float(h1);
                float l2f = a2 - __bfloat162float(h2);
                float l3f = a3 - __bfloat162float(h3);
                uint32_t hi01 = ((uint32_t)__bfloat16_as_ushort(h1) << 16) | __bfloat16_as_ushort(h0);
                uint32_t hi23 = ((uint32_t)__bfloat16_as_ushort(h3) << 16) | __bfloat16_as_ushort(h2);
                uint32_t lo01 = ((uint32_t)__bfloat16_as_ushort(__float2bfloat16(l1f)) << 16) |
                                __bfloat16_as_ushort(__float2bfloat16(l0f));
                uint32_t lo23 = ((uint32_t)__bfloat16_as_ushort(__float2bfloat16(l3f)) << 16) |
                                __bfloat16_as_ushort(__float2bfloat16(l2f));
                uint32_t off = SWZ128((uint32_t)(row * 128 + c4 * 8));
                *reinterpret_cast<uint2*>(dsm + OFF_AH + off) = make_uint2(hi01, hi23);
                *reinterpret_cast<uint2*>(dsm + OFF_AL + off) = make_uint2(lo01, lo23);
            }
            // ---- fill B hi/lo: 4 panels x 64 k x 64 h (128B rows), SW128 ----
            #pragma unroll
            for (int t = 0; t < 8; ++t) {
                int i = tid + t * 256;            // 0..2047 (16B chunks)
                int panel = i >> 9, rem = i & 511, row = rem >> 3, c = rem & 7;
                int goff = (kc * 64 + row) * HH + panel * 64 + c * 8;
                uint32_t soff = panel * 8192 + SWZ128((uint32_t)(row * 128 + c * 16));
                *reinterpret_cast<uint4*>(dsm + OFF_BH + soff) =
                    *reinterpret_cast<const uint4*>(&g_Wdh[goff]);
                *reinterpret_cast<uint4*>(dsm + OFF_BL + soff) =
                    *reinterpret_cast<const uint4*>(&g_Wdl[goff]);
            }
            __syncthreads();

            // ---- mma: 4 k-steps of 16 ----
            #pragma unroll
            for (int ks = 0; ks < 4; ++ks) {
                const int k0 = ks * 16;
                uint32_t ah[4][4], al[4][4];
                #pragma unroll
                for (int m = 0; m < 4; ++m) {
                    uint32_t offA = SWZ128((uint32_t)((a_row + m * 16) * 128 + k0 * 2 + a_cb));
                    ldm_x4(ah[m], sb + OFF_AH + offA);
                    ldm_x4(al[m], sb + OFF_AL + offA);
                }
                #pragma unroll
                for (int nb = 0; nb < 4; ++nb) {
                    uint32_t offB = wh * 8192 +
                        SWZ128((uint32_t)((k0 + b_kr) * 128 + nb * 32 + b_hb));
                    uint32_t bh[4], bl[4];
                    ldm_x4t(bh, sb + OFF_BH + offB);
                    ldm_x4t(bl, sb + OFF_BL + offB);
                    #pragma unroll
                    for (int m = 0; m < 4; ++m) {
                        mma16816(acc[m][2 * nb],     ah[m], bh);
                        mma16816(acc[m][2 * nb + 1], ah[m], bh + 2);
                        mma16816(acc[m][2 * nb],     ah[m], bl);
                        mma16816(acc[m][2 * nb + 1], ah[m], bl + 2);
                        mma16816(acc[m][2 * nb],     al[m], bh);
                        mma16816(acc[m][2 * nb + 1], al[m], bh + 2);
                    }
                }
            }
        }
        // ---- epilogue: sd[q] += sum_h tanh(T[q,h]) * vd[h] ----
        #pragma unroll
        for (int m = 0; m < 4; ++m) {
            float s0 = 0.f, s1 = 0.f;
            #pragma unroll
            for (int n = 0; n < 8; ++n) {
                int h = wh * 64 + n * 8 + (lane & 3) * 2;
                s0 = fmaf(tanh_fast(acc[m][n][0]), vd_s[h],     s0);
                s0 = fmaf(tanh_fast(acc[m][n][1]), vd_s[h + 1], s0);
                s1 = fmaf(tanh_fast(acc[m][n][2]), vd_s[h],     s1);
                s1 = fmaf(tanh_fast(acc[m][n][3]), vd_s[h + 1], s1);
            }
            s0 += __shfl_xor_sync(0xffffffffu, s0, 1);
            s0 += __shfl_xor_sync(0xffffffffu, s0, 2);
            s1 += __shfl_xor_sync(0xffffffffu, s1, 1);
            s1 += __shfl_xor_sync(0xffffffffu, s1, 2);
            if ((lane & 3) == 0) {
                int q = qh * 128 + wq * 64 + m * 16 + (lane >> 2);
                atomicAdd(&sdp[q], s0);
                atomicAdd(&sdp[q + 8], s1);
            }
        }
    }
    __syncthreads();
    g_SD[(b * LL + p) * LL + tid] = sdp[tid];
}

// ======================= kernel 3: fused c/m/b + softmax + attend (2 p per CTA) =======================
__device__ __forceinline__ float block_reduce(float v, bool is_max, float* rbuf,
                                              int lane, int wrp) {
    #pragma unroll
    for (int o = 16; o; o >>= 1) {
        float u = __shfl_xor_sync(0xffffffffu, v, o);
        v = is_max ? fmaxf(v, u) : (v + u);
    }
    if (lane == 0) rbuf[wrp] = v;
    __syncthreads();
    if (threadIdx.x == 0) {
        float r = rbuf[0];
        #pragma unroll
        for (int i = 1; i < 8; ++i) r = is_max ? fmaxf(r, rbuf[i]) : (r + rbuf[i]);
        rbuf[0] = r;
    }
    __syncthreads();
    float r = rbuf[0];
    __syncthreads();
    return r;
}

__global__ __launch_bounds__(256)
void fused_kernel(const float* __restrict__ Hp, const float* __restrict__ Hq,
                  const float* __restrict__ vc, const float* __restrict__ vm,
                  float* __restrict__ out) {
    const int p0 = blockIdx.x * 2, b = blockIdx.y;
    const int tid = threadIdx.x;
    const int lane = tid & 31, wrp = tid >> 5;

    __shared__ float hp[2][DD], s2r[2][HH], m2r[2][HH];
    __shared__ float vcs[HH], vms[HH];
    __shared__ float sco[2][4][LL];    // [p][branch: c,b,d,m][q]
    __shared__ float rbuf[8];

    #pragma unroll
    for (int j = 0; j < 2; ++j) {
        hp [j][tid] = Hp  [(b * LL + p0 + j) * DD + tid];
        s2r[j][tid] = g_S2[(b * LL + p0 + j) * HH + tid];
        m2r[j][tid] = g_M2[(b * LL + p0 + j) * HH + tid];
        sco[j][2][tid] = g_SD[(b * LL + p0 + j) * LL + tid];
    }
    vcs[tid] = vc[tid]; vms[tid] = vm[tid];
    __syncthreads();

    // ---- branches c, m, b scores (warp per q, lanes over h, both p) ----
    for (int qi = 0; qi < 32; ++qi) {
        int q = wrp * 32 + qi;
        const float* s1row = &g_S1[(b * LL + q) * HH];
        const float* m1row = &g_M1[(b * LL + q) * HH];
        const float* grow  = &g_G [(b * LL + q) * HH];
        float ac[2] = {0.f, 0.f}, am[2] = {0.f, 0.f}, ab[2] = {0.f, 0.f};
        #pragma unroll
        for (int it = 0; it < 8; ++it) {
            int h = lane + 32 * it;
            float s1v = s1row[h], m1v = m1row[h], gv = grow[h];
            float vch = vcs[h], vmh = vms[h];
            #pragma unroll
            for (int j = 0; j < 2; ++j) {
                ac[j] = fmaf(tanh_fast(s1v + s2r[j][h]), vch, ac[j]);
                am[j] = fmaf(tanh_fast(m1v - m2r[j][h]), vmh, am[j]);
                ab[j] = fmaf(hp[j][h], gv, ab[j]);
            }
        }
        #pragma unroll
        for (int o = 16; o; o >>= 1) {
            #pragma unroll
            for (int j = 0; j < 2; ++j) {
                ac[j] += __shfl_xor_sync(0xffffffffu, ac[j], o);
                am[j] += __shfl_xor_sync(0xffffffffu, am[j], o);
                ab[j] += __shfl_xor_sync(0xffffffffu, ab[j], o);
            }
        }
        if (lane == 0) {
            #pragma unroll
            for (int j = 0; j < 2; ++j) {
                sco[j][0][q] = ac[j]; sco[j][1][q] = ab[j]; sco[j][3][q] = am[j];
            }
        }
    }
    __syncthreads();

    // ---- softmax over q (8 arrays) ----
    #pragma unroll
    for (int j = 0; j < 2; ++j)
        #pragma unroll
        for (int br = 0; br < 4; ++br) {
            float v = sco[j][br][tid];
            __syncthreads();
            float mx  = block_reduce(v, true,  rbuf, lane, wrp);
            float e   = __expf(v - mx);
            float sum = block_reduce(e, false, rbuf, lane, wrp);
            sco[j][br][tid] = e / sum;
        }
    __syncthreads();

    // ---- attend: out[d] = sum_q w[q] * Hq[b,q,d] (Hq loads shared across 8) ----
    float o0[4] = {0.f, 0.f, 0.f, 0.f}, o1[4] = {0.f, 0.f, 0.f, 0.f};
    const float* hqb = &Hq[(b * LL) * DD + tid];
    for (int q = 0; q < LL; ++q) {
        float hq = hqb[q * DD];
        #pragma unroll
        for (int br = 0; br < 4; ++br) {
            o0[br] = fmaf(sco[0][br][q], hq, o0[br]);
            o1[br] = fmaf(sco[1][br][q], hq, o1[br]);
        }
    }
    const int BR = BB * LL * DD;
    #pragma unroll
    for (int br = 0; br < 4; ++br) {
        out[br * BR + (b * LL + p0 + 0) * DD + tid] = o0[br];
        out[br * BR + (b * LL + p0 + 1) * DD + tid] = o1[br];
    }
}

// ======================= launch =======================
extern "C" void kernel_launch(void* const* d_in, const int* in_sizes, int n_in,
                              void* d_out, int out_size) {
    (void)in_sizes; (void)n_in; (void)out_size;
    const float* Hp  = (const float*)d_in[0];
    const float* Hq  = (const float*)d_in[1];
    const float* Wc1 = (const float*)d_in[2];
    const float* Wc2 = (const float*)d_in[3];
    const float* vc  = (const float*)d_in[4];
    const float* Wb  = (const float*)d_in[5];
    const float* Wd  = (const float*)d_in[6];
    const float* vd  = (const float*)d_in[7];
    const float* Wm  = (const float*)d_in[8];
    const float* vm  = (const float*)d_in[9];
    float* out = (float*)d_out;

    static bool attr_set = false;
    if (!attr_set) {
        cudaFuncSetAttribute(branchd_kernel,
                             cudaFuncAttributeMaxDynamicSharedMemorySize, SMEM_D);
        attr_set = true;
    }

    prep_wd_kernel<<<DD, HH>>>(Wd);

    dim3 gproj(16, 4, 5);
    proj_kernel<<<gproj, 256>>>(Hp, Hq, Wc1, Wc2, Wb, Wm);

    dim3 gd(LL, BB);
    branchd_kernel<<<gd, 256, SMEM_D>>>(Hp, Hq, vd);

    dim3 gf(LL / 2, BB);
    fused_kernel<<<gf, 256>>>(Hp, Hq, vc, vm, out);
}

// round 4
// speedup vs baseline: 2.8090x; 1.4307x over previous
#include <cuda_runtime.h>
#include <cuda_bf16.h>
#include <cstdint>

// Problem: B=4, Lp=Lq=256, D=256, H=256.
// Inputs: Hp, Hq, Wc1, Wc2, vc, Wb, Wd, vd, Wm, vm (all fp32)
// Output: concat(qc, qb, qd, qm), each (B, Lp, D) fp32.

#define BB 4
#define LL 256
#define DD 256
#define HH 256

// -------- scratch (static device globals; no allocation allowed) --------
__device__ float g_S1[BB * LL * HH];  // Hq @ Wc1
__device__ float g_S2[BB * LL * HH];  // Hp @ Wc2
__device__ float g_G [BB * LL * HH];  // Hq @ Wb
__device__ float g_M1[BB * LL * HH];  // Hq @ Wm
__device__ float g_M2[BB * LL * HH];  // Hp @ Wm
__device__ float g_SD[BB * LL * LL];  // branch-d raw scores [b][p][q]
__device__ float g_SC[BB * LL * LL];  // branch-c raw scores
__device__ float g_SB[BB * LL * LL];  // branch-b raw scores
__device__ float g_SM[BB * LL * LL];  // branch-m raw scores
__device__ __nv_bfloat16 g_Wdh[DD * HH];  // Wd split high [k][h]
__device__ __nv_bfloat16 g_Wdl[DD * HH];  // Wd split low  [k][h]

// ======================= helpers =======================
__device__ __forceinline__ uint32_t smem_u32(const void* p) {
    uint32_t a;
    asm("{ .reg .u64 t; cvta.to.shared.u64 t, %1; cvt.u32.u64 %0, t; }"
        : "=r"(a) : "l"(p));
    return a;
}

__device__ __forceinline__ float tanh_fast(float x) {
    float y;
    asm("tanh.approx.f32 %0, %1;" : "=f"(y) : "f"(x));
    return y;
}

#define SWZ128(off) ((off) ^ (((off) >> 3) & 0x70))

#define CP_ASYNC16(dst_u32, src_ptr) \
    asm volatile("cp.async.cg.shared.global [%0], [%1], 16;" \
                 :: "r"(dst_u32), "l"(src_ptr) : "memory")
#define CP_COMMIT() asm volatile("cp.async.commit_group;" ::: "memory")
#define CP_WAIT0()  asm volatile("cp.async.wait_group 0;" ::: "memory")
#define CP_WAIT1()  asm volatile("cp.async.wait_group 1;" ::: "memory")

__device__ __forceinline__ void ldm_x4(uint32_t* r, uint32_t addr) {
    asm volatile("ldmatrix.sync.aligned.m8n8.x4.shared.b16 {%0,%1,%2,%3}, [%4];"
                 : "=r"(r[0]), "=r"(r[1]), "=r"(r[2]), "=r"(r[3]) : "r"(addr));
}

__device__ __forceinline__ void ldm_x4t(uint32_t* r, uint32_t addr) {
    asm volatile("ldmatrix.sync.aligned.m8n8.x4.trans.shared.b16 {%0,%1,%2,%3}, [%4];"
                 : "=r"(r[0]), "=r"(r[1]), "=r"(r[2]), "=r"(r[3]) : "r"(addr));
}

__device__ __forceinline__ void mma16816(float* d, const uint32_t* a, const uint32_t* b) {
    asm volatile(
        "mma.sync.aligned.m16n8k16.row.col.f32.bf16.bf16.f32 "
        "{%0,%1,%2,%3}, {%4,%5,%6,%7}, {%8,%9}, {%0,%1,%2,%3};"
        : "+f"(d[0]), "+f"(d[1]), "+f"(d[2]), "+f"(d[3])
        : "r"(a[0]), "r"(a[1]), "r"(a[2]), "r"(a[3]), "r"(b[0]), "r"(b[1]));
}

// ======================= kernel 0: split Wd into bf16 hi/lo =======================
__global__ void prep_wd_kernel(const float* __restrict__ Wd) {
    int k = blockIdx.x, h = threadIdx.x;
    float w = Wd[k * HH + h];
    __nv_bfloat16 hi = __float2bfloat16(w);
    g_Wdh[k * HH + h] = hi;
    g_Wdl[k * HH + h] = __float2bfloat16(w - __bfloat162float(hi));
}

// ======================= kernel 1: 5 projection GEMMs =======================
__global__ void proj_kernel(const float* __restrict__ Hp, const float* __restrict__ Hq,
                            const float* __restrict__ Wc1, const float* __restrict__ Wc2,
                            const float* __restrict__ Wb,  const float* __restrict__ Wm) {
    const float* A; const float* W; float* C;
    switch (blockIdx.z) {
        case 0:  A = Hq; W = Wc1; C = g_S1; break;
        case 1:  A = Hp; W = Wc2; C = g_S2; break;
        case 2:  A = Hq; W = Wb;  C = g_G;  break;
        case 3:  A = Hq; W = Wm;  C = g_M1; break;
        default: A = Hp; W = Wm;  C = g_M2; break;
    }
    const int mb = blockIdx.x * 64, nb = blockIdx.y * 64;
    const int tid = threadIdx.x, ty = tid >> 4, tx = tid & 15;

    __shared__ float As[16][68];
    __shared__ float Bs[16][68];

    float acc[4][4] = {};
    for (int kt = 0; kt < 16; ++kt) {
        {
            int m = tid >> 2, k4 = (tid & 3) * 4;
            float4 v = *reinterpret_cast<const float4*>(&A[(mb + m) * 256 + kt * 16 + k4]);
            As[k4 + 0][m] = v.x; As[k4 + 1][m] = v.y;
            As[k4 + 2][m] = v.z; As[k4 + 3][m] = v.w;
        }
        {
            int k = tid >> 4, n4 = (tid & 15) * 4;
            float4 v = *reinterpret_cast<const float4*>(&W[(kt * 16 + k) * 256 + nb + n4]);
            *reinterpret_cast<float4*>(&Bs[k][n4]) = v;
        }
        __syncthreads();
        #pragma unroll
        for (int k = 0; k < 16; ++k) {
            float a[4], bv[4];
            #pragma unroll
            for (int i = 0; i < 4; ++i) a[i] = As[k][ty + 16 * i];
            #pragma unroll
            for (int j = 0; j < 4; ++j) bv[j] = Bs[k][tx + 16 * j];
            #pragma unroll
            for (int i = 0; i < 4; ++i)
                #pragma unroll
                for (int j = 0; j < 4; ++j) acc[i][j] = fmaf(a[i], bv[j], acc[i][j]);
        }
        __syncthreads();
    }
    #pragma unroll
    for (int i = 0; i < 4; ++i)
        #pragma unroll
        for (int j = 0; j < 4; ++j)
            C[(mb + ty + 16 * i) * 256 + nb + tx + 16 * j] = acc[i][j];
}

// ======================= kernel 2: branch d via mma.sync (split bf16, pipelined) =======================
static constexpr int BUFSZ   = 98304;             // AH 16K | AL 16K | BH 32K | BL 32K
static constexpr int OFF_HP  = 2 * BUFSZ;         // 196608
static constexpr int OFF_VD  = OFF_HP + 1024;
static constexpr int OFF_SDP = OFF_VD + 1024;
static constexpr int SMEM_D  = OFF_SDP + 1024;    // 199680

__device__ __forceinline__ void fill_A(char* base, const float* __restrict__ hq_b,
                                       const float* hp_s, int qh, int kc, int tid) {
    #pragma unroll
    for (int t = 0; t < 8; ++t) {
        int i = tid + t * 256;            // 0..2047
        int row = i >> 4, c4 = i & 15;
        int kg = kc * 64 + c4 * 4;
        float4 v = *reinterpret_cast<const float4*>(&hq_b[(qh * 128 + row) * DD + kg]);
        float a0 = v.x * hp_s[kg + 0];
        float a1 = v.y * hp_s[kg + 1];
        float a2 = v.z * hp_s[kg + 2];
        float a3 = v.w * hp_s[kg + 3];
        __nv_bfloat16 h0 = __float2bfloat16(a0), h1 = __float2bfloat16(a1);
        __nv_bfloat16 h2 = __float2bfloat16(a2), h3 = __float2bfloat16(a3);
        float l0f = a0 - __bfloat162float(h0);
        float l1f = a1 - __bfloat162float(h1);
        float l2f = a2 - __bfloat162float(h2);
        float l3f = a3 - __bfloat162float(h3);
        uint32_t hi01 = ((uint32_t)__bfloat16_as_ushort(h1) << 16) | __bfloat16_as_ushort(h0);
        uint32_t hi23 = ((uint32_t)__bfloat16_as_ushort(h3) << 16) | __bfloat16_as_ushort(h2);
        uint32_t lo01 = ((uint32_t)__bfloat16_as_ushort(__float2bfloat16(l1f)) << 16) |
                        __bfloat16_as_ushort(__float2bfloat16(l0f));
        uint32_t lo23 = ((uint32_t)__bfloat16_as_ushort(__float2bfloat16(l3f)) << 16) |
                        __bfloat16_as_ushort(__float2bfloat16(l2f));
        uint32_t off = SWZ128((uint32_t)(row * 128 + c4 * 8));
        *reinterpret_cast<uint2*>(base + off)         = make_uint2(hi01, hi23);
        *reinterpret_cast<uint2*>(base + 16384 + off) = make_uint2(lo01, lo23);
    }
}

__device__ __forceinline__ void fill_B(char* base, int kc, int tid) {
    uint32_t bH = smem_u32(base + 32768);
    uint32_t bL = smem_u32(base + 65536);
    #pragma unroll
    for (int t = 0; t < 8; ++t) {
        int i = tid + t * 256;            // 0..2047 (16B chunks)
        int panel = i >> 9, rem = i & 511, row = rem >> 3, c = rem & 7;
        int goff = (kc * 64 + row) * HH + panel * 64 + c * 8;
        uint32_t soff = panel * 8192 + SWZ128((uint32_t)(row * 128 + c * 16));
        CP_ASYNC16(bH + soff, (const void*)&g_Wdh[goff]);
        CP_ASYNC16(bL + soff, (const void*)&g_Wdl[goff]);
    }
}

__device__ __forceinline__ void mma_ks(int ks, uint32_t aH, uint32_t aL,
                                       uint32_t bH, uint32_t bL,
                                       int a_row, int a_cb, int b_kr, int b_hb, int wh,
                                       float (&acc)[4][8][4]) {
    const int k0 = ks * 16;
    uint32_t ah[4][4], al[4][4];
    #pragma unroll
    for (int m = 0; m < 4; ++m) {
        uint32_t offA = SWZ128((uint32_t)((a_row + m * 16) * 128 + k0 * 2 + a_cb));
        ldm_x4(ah[m], aH + offA);
        ldm_x4(al[m], aL + offA);
    }
    #pragma unroll
    for (int nb = 0; nb < 4; ++nb) {
        uint32_t offB = wh * 8192 + SWZ128((uint32_t)((k0 + b_kr) * 128 + nb * 32 + b_hb));
        uint32_t bh[4], bl[4];
        ldm_x4t(bh, bH + offB);
        ldm_x4t(bl, bL + offB);
        #pragma unroll
        for (int m = 0; m < 4; ++m) {
            mma16816(acc[m][2 * nb],     ah[m], bh);
            mma16816(acc[m][2 * nb + 1], ah[m], bh + 2);
            mma16816(acc[m][2 * nb],     ah[m], bl);
            mma16816(acc[m][2 * nb + 1], ah[m], bl + 2);
            mma16816(acc[m][2 * nb],     al[m], bh);
            mma16816(acc[m][2 * nb + 1], al[m], bh + 2);
        }
    }
}

__global__ __launch_bounds__(256, 1)
void branchd_kernel(const float* __restrict__ Hp, const float* __restrict__ Hq,
                    const float* __restrict__ vd) {
    extern __shared__ char dsm[];
    const uint32_t sb = smem_u32(dsm);
    const int p = blockIdx.x, b = blockIdx.y;
    const int tid = threadIdx.x, lane = tid & 31, warp = tid >> 5;
    const int wq = warp >> 2, wh = warp & 3;

    float* hp_s = reinterpret_cast<float*>(dsm + OFF_HP);
    float* vd_s = reinterpret_cast<float*>(dsm + OFF_VD);
    float* sdp  = reinterpret_cast<float*>(dsm + OFF_SDP);
    hp_s[tid] = Hp[(b * LL + p) * DD + tid];
    vd_s[tid] = vd[tid];
    sdp[tid] = 0.f;
    __syncthreads();

    const int a_row = wq * 64 + (lane & 15);
    const int a_cb  = (lane >> 4) * 16;
    const int b_kr  = ((lane >> 3) & 1) * 8 + (lane & 7);
    const int b_hb  = (lane >> 4) * 16;

    const float* hq_b = Hq + (b * LL) * DD;

    // prologue: fill tile 0
    fill_A(dsm, hq_b, hp_s, 0, 0, tid);
    fill_B(dsm, 0, tid);
    CP_COMMIT();
    CP_WAIT0();
    __syncthreads();

    for (int qh = 0; qh < 2; ++qh) {
        float acc[4][8][4];
        #pragma unroll
        for (int m = 0; m < 4; ++m)
            #pragma unroll
            for (int n = 0; n < 8; ++n)
                #pragma unroll
                for (int e = 0; e < 4; ++e) acc[m][n][e] = 0.f;

        for (int kc = 0; kc < 4; ++kc) {
            const int t = qh * 4 + kc;
            const uint32_t aH = sb + (uint32_t)(t & 1) * BUFSZ;
            const uint32_t aL = aH + 16384, bH = aH + 32768, bL = aH + 65536;

            mma_ks(0, aH, aL, bH, bL, a_row, a_cb, b_kr, b_hb, wh, acc);

            if (t < 7) {   // fill next tile while tensor pipe drains ks0
                char* nbase = dsm + ((t + 1) & 1) * BUFSZ;
                fill_A(nbase, hq_b, hp_s, (t + 1) >> 2, (t + 1) & 3, tid);
                fill_B(nbase, (t + 1) & 3, tid);
                CP_COMMIT();
            }

            mma_ks(1, aH, aL, bH, bL, a_row, a_cb, b_kr, b_hb, wh, acc);
            mma_ks(2, aH, aL, bH, bL, a_row, a_cb, b_kr, b_hb, wh, acc);
            mma_ks(3, aH, aL, bH, bL, a_row, a_cb, b_kr, b_hb, wh, acc);

            if (t < 7) CP_WAIT0();
            __syncthreads();
        }
        // epilogue: sd[q] += sum_h tanh(T[q,h]) * vd[h]
        #pragma unroll
        for (int m = 0; m < 4; ++m) {
            float s0 = 0.f, s1 = 0.f;
            #pragma unroll
            for (int n = 0; n < 8; ++n) {
                int h = wh * 64 + n * 8 + (lane & 3) * 2;
                s0 = fmaf(tanh_fast(acc[m][n][0]), vd_s[h],     s0);
                s0 = fmaf(tanh_fast(acc[m][n][1]), vd_s[h + 1], s0);
                s1 = fmaf(tanh_fast(acc[m][n][2]), vd_s[h],     s1);
                s1 = fmaf(tanh_fast(acc[m][n][3]), vd_s[h + 1], s1);
            }
            s0 += __shfl_xor_sync(0xffffffffu, s0, 1);
            s0 += __shfl_xor_sync(0xffffffffu, s0, 2);
            s1 += __shfl_xor_sync(0xffffffffu, s1, 1);
            s1 += __shfl_xor_sync(0xffffffffu, s1, 2);
            if ((lane & 3) == 0) {
                int q = qh * 128 + wq * 64 + m * 16 + (lane >> 2);
                atomicAdd(&sdp[q], s0);
                atomicAdd(&sdp[q + 8], s1);
            }
        }
    }
    __syncthreads();
    g_SD[(b * LL + p) * LL + tid] = sdp[tid];
}

// ======================= kernel 3 (F1): scores c, b, m — tiled + cp.async =======================
// grid (4 q-tiles, 16 p-tiles, 4 b); CTA = 16 p x 64 q. Warp w handles p = p0+w+8*pi.
__global__ __launch_bounds__(256)
void score_kernel(const float* __restrict__ Hp,
                  const float* __restrict__ vc, const float* __restrict__ vm) {
    __shared__ float s1c[2][8][256];
    __shared__ float m1c[2][8][256];
    __shared__ float gc [2][8][256];

    const int q0 = blockIdx.x * 64, p0 = blockIdx.y * 16, b = blockIdx.z;
    const int tid = threadIdx.x, lane = tid & 31, w = tid >> 5;

    // register-resident per-p rows and v vectors
    float s2v[2][8], m2v[2][8], hpv[2][8], vcv[8], vmv[8];
    #pragma unroll
    for (int i = 0; i < 8; ++i) {
        int h = lane + 32 * i;
        vcv[i] = vc[h];
        vmv[i] = vm[h];
        #pragma unroll
        for (int pi = 0; pi < 2; ++pi) {
            int p = p0 + w + 8 * pi;
            s2v[pi][i] = g_S2[(b * LL + p) * HH + h];
            m2v[pi][i] = g_M2[(b * LL + p) * HH + h];
            hpv[pi][i] = Hp  [(b * LL + p) * DD + h];
        }
    }

    // cp.async chunk issuer: chunk c = 8 q-rows of S1/M1/G
    auto issue_chunk = [&](int c, int cb) {
        #pragma unroll
        for (int t = 0; t < 6; ++t) {
            int i = tid + t * 256;        // 0..1535
            int arr = i >> 9, rem = i & 511, row = rem >> 6, c16 = rem & 63;
            int gidx = (b * LL + q0 + c * 8 + row) * HH + c16 * 4;
            const float* src;
            float* dst;
            if (arr == 0)      { src = &g_S1[gidx]; dst = &s1c[cb][row][c16 * 4]; }
            else if (arr == 1) { src = &g_M1[gidx]; dst = &m1c[cb][row][c16 * 4]; }
            else               { src = &g_G [gidx]; dst = &gc [cb][row][c16 * 4]; }
            CP_ASYNC16(smem_u32(dst), (const void*)src);
        }
        CP_COMMIT();
    };

    issue_chunk(0, 0);
    for (int c = 0; c < 8; ++c) {
        int cb = c & 1;
        if (c < 7) { issue_chunk(c + 1, (c + 1) & 1); CP_WAIT1(); }
        else       { CP_WAIT0(); }
        __syncthreads();

        #pragma unroll
        for (int pi = 0; pi < 2; ++pi) {
            #pragma unroll
            for (int r = 0; r < 8; ++r) {
                float ac = 0.f, am = 0.f, ab = 0.f;
                #pragma unroll
                for (int i = 0; i < 8; ++i) {
                    int h = lane + 32 * i;
                    float s1 = s1c[cb][r][h];
                    float m1 = m1c[cb][r][h];
                    float g  = gc [cb][r][h];
                    ac = fmaf(tanh_fast(s1 + s2v[pi][i]), vcv[i], ac);
                    am = fmaf(tanh_fast(m1 - m2v[pi][i]), vmv[i], am);
                    ab = fmaf(hpv[pi][i], g, ab);
                }
                #pragma unroll
                for (int o = 16; o; o >>= 1) {
                    ac += __shfl_xor_sync(0xffffffffu, ac, o);
                    am += __shfl_xor_sync(0xffffffffu, am, o);
                    ab += __shfl_xor_sync(0xffffffffu, ab, o);
                }
                if (lane == 0) {
                    int p = p0 + w + 8 * pi;
                    int q = q0 + c * 8 + r;
                    int idx = (b * LL + p) * LL + q;
                    g_SC[idx] = ac;
                    g_SB[idx] = ab;
                    g_SM[idx] = am;
                }
            }
        }
        __syncthreads();
    }
}

// ======================= kernel 4 (F2): softmax + attend, all 4 branches =======================
// grid (32 p-tiles, 4 b); CTA = 8 p x 4 branches. Weights staged q-major in smem.
__global__ __launch_bounds__(256)
void attend_kernel(const float* __restrict__ Hq, float* __restrict__ out) {
    __shared__ float wsm[256][36];   // [q][slot=p*4+br], padded

    const int p0 = blockIdx.x * 8, b = blockIdx.y;
    const int tid = threadIdx.x, lane = tid & 31, w = tid >> 5;

    // load scores (coalesced) and transpose into q-major smem
    const float* srcs[4] = {g_SC, g_SB, g_SD, g_SM};
    #pragma unroll
    for (int t = 0; t < 32; ++t) {
        int i = tid + t * 256;          // 0..8191: (p, br, q)
        int p = i >> 10, br = (i >> 8) & 3, q = i & 255;
        wsm[q][p * 4 + br] = srcs[br][(b * LL + p0 + p) * LL + q];
    }
    __syncthreads();

    // softmax per slot: warp w handles slots w, w+8, w+16, w+24
    #pragma unroll
    for (int s = 0; s < 4; ++s) {
        int slot = w + 8 * s;
        float v[8];
        #pragma unroll
        for (int i = 0; i < 8; ++i) v[i] = wsm[lane + 32 * i][slot];
        float mx = v[0];
        #pragma unroll
        for (int i = 1; i < 8; ++i) mx = fmaxf(mx, v[i]);
        #pragma unroll
        for (int o = 16; o; o >>= 1) mx = fmaxf(mx, __shfl_xor_sync(0xffffffffu, mx, o));
        float sum = 0.f;
        #pragma unroll
        for (int i = 0; i < 8; ++i) { v[i] = __expf(v[i] - mx); sum += v[i]; }
        #pragma unroll
        for (int o = 16; o; o >>= 1) sum += __shfl_xor_sync(0xffffffffu, sum, o);
        float inv = 1.0f / sum;
        #pragma unroll
        for (int i = 0; i < 8; ++i) wsm[lane + 32 * i][slot] = v[i] * inv;
    }
    __syncthreads();

    // attend: thread = d; 32 accumulators (8 p x 4 br)
    float acc[32];
    #pragma unroll
    for (int s = 0; s < 32; ++s) acc[s] = 0.f;
    const float* hqb = &Hq[(b * LL) * DD + tid];
    #pragma unroll 4
    for (int q = 0; q < LL; ++q) {
        float hq = hqb[q * DD];
        #pragma unroll
        for (int j = 0; j < 8; ++j) {
            float4 wv = *reinterpret_cast<const float4*>(&wsm[q][j * 4]);
            acc[j * 4 + 0] = fmaf(wv.x, hq, acc[j * 4 + 0]);
            acc[j * 4 + 1] = fmaf(wv.y, hq, acc[j * 4 + 1]);
            acc[j * 4 + 2] = fmaf(wv.z, hq, acc[j * 4 + 2]);
            acc[j * 4 + 3] = fmaf(wv.w, hq, acc[j * 4 + 3]);
        }
    }
    const int BR = BB * LL * DD;
    #pragma unroll
    for (int p = 0; p < 8; ++p)
        #pragma unroll
        for (int br = 0; br < 4; ++br)
            out[br * BR + (b * LL + p0 + p) * DD + tid] = acc[p * 4 + br];
}

// ======================= launch =======================
extern "C" void kernel_launch(void* const* d_in, const int* in_sizes, int n_in,
                              void* d_out, int out_size) {
    (void)in_sizes; (void)n_in; (void)out_size;
    const float* Hp  = (const float*)d_in[0];
    const float* Hq  = (const float*)d_in[1];
    const float* Wc1 = (const float*)d_in[2];
    const float* Wc2 = (const float*)d_in[3];
    const float* vc  = (const float*)d_in[4];
    const float* Wb  = (const float*)d_in[5];
    const float* Wd  = (const float*)d_in[6];
    const float* vd  = (const float*)d_in[7];
    const float* Wm  = (const float*)d_in[8];
    const float* vm  = (const float*)d_in[9];
    float* out = (float*)d_out;

    cudaFuncSetAttribute(branchd_kernel,
                         cudaFuncAttributeMaxDynamicSharedMemorySize, SMEM_D);

    prep_wd_kernel<<<DD, HH>>>(Wd);

    dim3 gproj(16, 4, 5);
    proj_kernel<<<gproj, 256>>>(Hp, Hq, Wc1, Wc2, Wb, Wm);

    dim3 gd(LL, BB);
    branchd_kernel<<<gd, 256, SMEM_D>>>(Hp, Hq, vd);

    dim3 gs(4, 16, 4);
    score_kernel<<<gs, 256>>>(Hp, vc, vm);

    dim3 ga(32, 4);
    attend_kernel<<<ga, 256>>>(Hq, out);
}

// round 5
// speedup vs baseline: 3.2796x; 1.1675x over previous
#include <cuda_runtime.h>
#include <cuda_bf16.h>
#include <cstdint>

// Problem: B=4, Lp=Lq=256, D=256, H=256.
// Inputs: Hp, Hq, Wc1, Wc2, vc, Wb, Wd, vd, Wm, vm (all fp32)
// Output: concat(qc, qb, qd, qm), each (B, Lp, D) fp32.

#define BB 4
#define LL 256
#define DD 256
#define HH 256

// -------- scratch (static device globals; no allocation allowed) --------
__device__ float g_S1[BB * LL * HH];  // Hq @ Wc1
__device__ float g_S2[BB * LL * HH];  // Hp @ Wc2
__device__ float g_G [BB * LL * HH];  // Hq @ Wb
__device__ float g_M1[BB * LL * HH];  // Hq @ Wm
__device__ float g_M2[BB * LL * HH];  // Hp @ Wm
__device__ float g_SD[BB * LL * LL];  // branch-d raw scores [b][p][q]
__device__ float g_SC[BB * LL * LL];  // branch-c raw scores
__device__ float g_SB[BB * LL * LL];  // branch-b raw scores
__device__ float g_SM[BB * LL * LL];  // branch-m raw scores
__device__ uint32_t g_Wd32[HH * DD];  // Wd^T in tf32 bits [h][k]

// ======================= helpers =======================
__device__ __forceinline__ uint32_t smem_u32(const void* p) {
    uint32_t a;
    asm("{ .reg .u64 t; cvta.to.shared.u64 t, %1; cvt.u32.u64 %0, t; }"
        : "=r"(a) : "l"(p));
    return a;
}

__device__ __forceinline__ float tanh_fast(float x) {
    float y;
    asm("tanh.approx.f32 %0, %1;" : "=f"(y) : "f"(x));
    return y;
}

__device__ __forceinline__ uint32_t tf32_of(float f) {
    uint32_t u;
    asm("cvt.rna.tf32.f32 %0, %1;" : "=r"(u) : "f"(f));
    return u;
}

#define SWZ128(off) ((off) ^ (((off) >> 3) & 0x70))

#define CP_ASYNC16(dst_u32, src_ptr) \
    asm volatile("cp.async.cg.shared.global [%0], [%1], 16;" \
                 :: "r"(dst_u32), "l"(src_ptr) : "memory")
#define CP_COMMIT() asm volatile("cp.async.commit_group;" ::: "memory")
#define CP_WAIT0()  asm volatile("cp.async.wait_group 0;" ::: "memory")
#define CP_WAIT1()  asm volatile("cp.async.wait_group 1;" ::: "memory")

__device__ __forceinline__ void ldm_x4(uint32_t* r, uint32_t addr) {
    asm volatile("ldmatrix.sync.aligned.m8n8.x4.shared.b16 {%0,%1,%2,%3}, [%4];"
                 : "=r"(r[0]), "=r"(r[1]), "=r"(r[2]), "=r"(r[3]) : "r"(addr));
}

__device__ __forceinline__ void ldm_x2(uint32_t* r, uint32_t addr) {
    asm volatile("ldmatrix.sync.aligned.m8n8.x2.shared.b16 {%0,%1}, [%2];"
                 : "=r"(r[0]), "=r"(r[1]) : "r"(addr));
}

__device__ __forceinline__ void mma_tf32(float* d, const uint32_t* a, const uint32_t* b) {
    asm volatile(
        "mma.sync.aligned.m16n8k8.row.col.f32.tf32.tf32.f32 "
        "{%0,%1,%2,%3}, {%4,%5,%6,%7}, {%8,%9}, {%0,%1,%2,%3};"
        : "+f"(d[0]), "+f"(d[1]), "+f"(d[2]), "+f"(d[3])
        : "r"(a[0]), "r"(a[1]), "r"(a[2]), "r"(a[3]), "r"(b[0]), "r"(b[1]));
}

// ======================= kernel 0: Wd^T -> tf32 =======================
__global__ void prep_wd_kernel(const float* __restrict__ Wd) {
    int k = blockIdx.x, h = threadIdx.x;
    g_Wd32[h * DD + k] = tf32_of(Wd[k * HH + h]);
}

// ======================= kernel 1: 5 projection GEMMs =======================
__global__ void proj_kernel(const float* __restrict__ Hp, const float* __restrict__ Hq,
                            const float* __restrict__ Wc1, const float* __restrict__ Wc2,
                            const float* __restrict__ Wb,  const float* __restrict__ Wm) {
    const float* A; const float* W; float* C;
    switch (blockIdx.z) {
        case 0:  A = Hq; W = Wc1; C = g_S1; break;
        case 1:  A = Hp; W = Wc2; C = g_S2; break;
        case 2:  A = Hq; W = Wb;  C = g_G;  break;
        case 3:  A = Hq; W = Wm;  C = g_M1; break;
        default: A = Hp; W = Wm;  C = g_M2; break;
    }
    const int mb = blockIdx.x * 64, nb = blockIdx.y * 64;
    const int tid = threadIdx.x, ty = tid >> 4, tx = tid & 15;

    __shared__ float As[16][68];
    __shared__ float Bs[16][68];

    float acc[4][4] = {};
    for (int kt = 0; kt < 16; ++kt) {
        {
            int m = tid >> 2, k4 = (tid & 3) * 4;
            float4 v = *reinterpret_cast<const float4*>(&A[(mb + m) * 256 + kt * 16 + k4]);
            As[k4 + 0][m] = v.x; As[k4 + 1][m] = v.y;
            As[k4 + 2][m] = v.z; As[k4 + 3][m] = v.w;
        }
        {
            int k = tid >> 4, n4 = (tid & 15) * 4;
            float4 v = *reinterpret_cast<const float4*>(&W[(kt * 16 + k) * 256 + nb + n4]);
            *reinterpret_cast<float4*>(&Bs[k][n4]) = v;
        }
        __syncthreads();
        #pragma unroll
        for (int k = 0; k < 16; ++k) {
            float a[4], bv[4];
            #pragma unroll
            for (int i = 0; i < 4; ++i) a[i] = As[k][ty + 16 * i];
            #pragma unroll
            for (int j = 0; j < 4; ++j) bv[j] = Bs[k][tx + 16 * j];
            #pragma unroll
            for (int i = 0; i < 4; ++i)
                #pragma unroll
                for (int j = 0; j < 4; ++j) acc[i][j] = fmaf(a[i], bv[j], acc[i][j]);
        }
        __syncthreads();
    }
    #pragma unroll
    for (int i = 0; i < 4; ++i)
        #pragma unroll
        for (int j = 0; j < 4; ++j)
            C[(mb + ty + 16 * i) * 256 + nb + tx + 16 * j] = acc[i][j];
}

// ======================= kernel 2: branch d via tf32 mma.sync (1 pass, pipelined) =======================
// Buffer: A (128q x 32k f32, SW128 128B rows) 16KB | B (256h x 32k f32) 32KB
static constexpr int BUFSZ   = 49152;
static constexpr int OFF_HP  = 2 * BUFSZ;         // 98304
static constexpr int OFF_VD  = OFF_HP + 1024;
static constexpr int OFF_SDP = OFF_VD + 1024;
static constexpr int SMEM_D  = OFF_SDP + 1024;    // 101376

__device__ __forceinline__ void fill_A(char* base, const float* __restrict__ hq_b,
                                       const float* hp_s, int qh, int kc, int tid) {
    #pragma unroll
    for (int t = 0; t < 4; ++t) {
        int i = tid + t * 256;            // 0..1023 chunks of 16B
        int row = i >> 3, c = i & 7;
        int kg = kc * 32 + c * 4;
        float4 v = *reinterpret_cast<const float4*>(&hq_b[(qh * 128 + row) * DD + kg]);
        uint4 r;
        r.x = tf32_of(v.x * hp_s[kg + 0]);
        r.y = tf32_of(v.y * hp_s[kg + 1]);
        r.z = tf32_of(v.z * hp_s[kg + 2]);
        r.w = tf32_of(v.w * hp_s[kg + 3]);
        *reinterpret_cast<uint4*>(base + SWZ128((uint32_t)(row * 128 + c * 16))) = r;
    }
}

__device__ __forceinline__ void fill_B(char* base, int kc, int tid) {
    uint32_t bB = smem_u32(base + 16384);
    #pragma unroll
    for (int t = 0; t < 8; ++t) {
        int i = tid + t * 256;            // 0..2047 chunks of 16B
        int row = i >> 3, c = i & 7;      // row = h, c = k-group
        int goff = row * DD + kc * 32 + c * 4;
        CP_ASYNC16(bB + SWZ128((uint32_t)(row * 128 + c * 16)), (const void*)&g_Wd32[goff]);
    }
}

__device__ __forceinline__ void mma_ks(int ks, uint32_t aA, uint32_t aB,
                                       int a_row, int a_cb, int b_row, int b_cb, int wh,
                                       float (&acc)[4][8][4]) {
    const int k0b = ks * 32;
    uint32_t a[4][4];
    #pragma unroll
    for (int m = 0; m < 4; ++m) {
        uint32_t offA = SWZ128((uint32_t)((a_row + m * 16) * 128 + k0b + a_cb));
        ldm_x4(a[m], aA + offA);
    }
    #pragma unroll
    for (int n = 0; n < 8; ++n) {
        uint32_t offB = SWZ128((uint32_t)((b_row + n * 8) * 128 + k0b + b_cb));
        uint32_t bf[2];
        ldm_x2(bf, aB + offB);
        #pragma unroll
        for (int m = 0; m < 4; ++m) mma_tf32(acc[m][n], a[m], bf);
    }
}

__global__ __launch_bounds__(256, 1)
void branchd_kernel(const float* __restrict__ Hp, const float* __restrict__ Hq,
                    const float* __restrict__ vd) {
    extern __shared__ char dsm[];
    const uint32_t sb = smem_u32(dsm);
    const int p = blockIdx.x, b = blockIdx.y;
    const int tid = threadIdx.x, lane = tid & 31, warp = tid >> 5;
    const int wq = warp >> 2, wh = warp & 3;

    float* hp_s = reinterpret_cast<float*>(dsm + OFF_HP);
    float* vd_s = reinterpret_cast<float*>(dsm + OFF_VD);
    float* sdp  = reinterpret_cast<float*>(dsm + OFF_SDP);
    hp_s[tid] = Hp[(b * LL + p) * DD + tid];
    vd_s[tid] = vd[tid];
    sdp[tid] = 0.f;
    __syncthreads();

    // ldmatrix lane addressing
    const int a_row = wq * 64 + (lane & 15);          // + m*16
    const int a_cb  = (lane >> 4) * 16;               // column-half byte
    const int b_row = wh * 64 + (lane & 7);           // + n*8
    const int b_cb  = ((lane >> 3) & 1) * 16;         // tile byte (x2)

    const float* hq_b = Hq + (b * LL) * DD;

    // prologue: fill tile 0
    fill_A(dsm, hq_b, hp_s, 0, 0, tid);
    fill_B(dsm, 0, tid);
    CP_COMMIT();
    CP_WAIT0();
    __syncthreads();

    for (int qh = 0; qh < 2; ++qh) {
        float acc[4][8][4];
        #pragma unroll
        for (int m = 0; m < 4; ++m)
            #pragma unroll
            for (int n = 0; n < 8; ++n)
                #pragma unroll
                for (int e = 0; e < 4; ++e) acc[m][n][e] = 0.f;

        for (int kc = 0; kc < 8; ++kc) {
            const int t = qh * 8 + kc;
            const uint32_t aA = sb + (uint32_t)(t & 1) * BUFSZ;
            const uint32_t aB = aA + 16384;

            mma_ks(0, aA, aB, a_row, a_cb, b_row, b_cb, wh, acc);

            if (t < 15) {   // fill next tile while tensor pipe drains
                char* nbase = dsm + ((t + 1) & 1) * BUFSZ;
                fill_A(nbase, hq_b, hp_s, (t + 1) >> 3, (t + 1) & 7, tid);
                fill_B(nbase, (t + 1) & 7, tid);
                CP_COMMIT();
            }

            mma_ks(1, aA, aB, a_row, a_cb, b_row, b_cb, wh, acc);
            mma_ks(2, aA, aB, a_row, a_cb, b_row, b_cb, wh, acc);
            mma_ks(3, aA, aB, a_row, a_cb, b_row, b_cb, wh, acc);

            if (t < 15) CP_WAIT0();
            __syncthreads();
        }
        // epilogue: sd[q] += sum_h tanh(T[q,h]) * vd[h]
        #pragma unroll
        for (int m = 0; m < 4; ++m) {
            float s0 = 0.f, s1 = 0.f;
            #pragma unroll
            for (int n = 0; n < 8; ++n) {
                int h = wh * 64 + n * 8 + (lane & 3) * 2;
                s0 = fmaf(tanh_fast(acc[m][n][0]), vd_s[h],     s0);
                s0 = fmaf(tanh_fast(acc[m][n][1]), vd_s[h + 1], s0);
                s1 = fmaf(tanh_fast(acc[m][n][2]), vd_s[h],     s1);
                s1 = fmaf(tanh_fast(acc[m][n][3]), vd_s[h + 1], s1);
            }
            s0 += __shfl_xor_sync(0xffffffffu, s0, 1);
            s0 += __shfl_xor_sync(0xffffffffu, s0, 2);
            s1 += __shfl_xor_sync(0xffffffffu, s1, 1);
            s1 += __shfl_xor_sync(0xffffffffu, s1, 2);
            if ((lane & 3) == 0) {
                int q = qh * 128 + wq * 64 + m * 16 + (lane >> 2);
                atomicAdd(&sdp[q], s0);
                atomicAdd(&sdp[q + 8], s1);
            }
        }
    }
    __syncthreads();
    g_SD[(b * LL + p) * LL + tid] = sdp[tid];
}

// ======================= kernel 3 (F1): scores c, b, m — tiled + cp.async =======================
__global__ __launch_bounds__(256, 2)
void score_kernel(const float* __restrict__ Hp,
                  const float* __restrict__ vc, const float* __restrict__ vm) {
    __shared__ float s1c[2][8][256];
    __shared__ float m1c[2][8][256];
    __shared__ float gc [2][8][256];

    const int q0 = blockIdx.x * 64, p0 = blockIdx.y * 16, b = blockIdx.z;
    const int tid = threadIdx.x, lane = tid & 31, w = tid >> 5;

    float s2v[2][8], m2v[2][8], hpv[2][8], vcv[8], vmv[8];
    #pragma unroll
    for (int i = 0; i < 8; ++i) {
        int h = lane + 32 * i;
        vcv[i] = vc[h];
        vmv[i] = vm[h];
        #pragma unroll
        for (int pi = 0; pi < 2; ++pi) {
            int p = p0 + w + 8 * pi;
            s2v[pi][i] = g_S2[(b * LL + p) * HH + h];
            m2v[pi][i] = g_M2[(b * LL + p) * HH + h];
            hpv[pi][i] = Hp  [(b * LL + p) * DD + h];
        }
    }

    auto issue_chunk = [&](int c, int cb) {
        #pragma unroll
        for (int t = 0; t < 6; ++t) {
            int i = tid + t * 256;        // 0..1535
            int arr = i >> 9, rem = i & 511, row = rem >> 6, c16 = rem & 63;
            int gidx = (b * LL + q0 + c * 8 + row) * HH + c16 * 4;
            const float* src;
            float* dst;
            if (arr == 0)      { src = &g_S1[gidx]; dst = &s1c[cb][row][c16 * 4]; }
            else if (arr == 1) { src = &g_M1[gidx]; dst = &m1c[cb][row][c16 * 4]; }
            else               { src = &g_G [gidx]; dst = &gc [cb][row][c16 * 4]; }
            CP_ASYNC16(smem_u32(dst), (const void*)src);
        }
        CP_COMMIT();
    };

    issue_chunk(0, 0);
    for (int c = 0; c < 8; ++c) {
        int cb = c & 1;
        if (c < 7) { issue_chunk(c + 1, (c + 1) & 1); CP_WAIT1(); }
        else       { CP_WAIT0(); }
        __syncthreads();

        #pragma unroll
        for (int pi = 0; pi < 2; ++pi) {
            #pragma unroll 2
            for (int r = 0; r < 8; ++r) {
                float ac = 0.f, am = 0.f, ab = 0.f;
                #pragma unroll
                for (int i = 0; i < 8; ++i) {
                    int h = lane + 32 * i;
                    float s1 = s1c[cb][r][h];
                    float m1 = m1c[cb][r][h];
                    float g  = gc [cb][r][h];
                    ac = fmaf(tanh_fast(s1 + s2v[pi][i]), vcv[i], ac);
                    am = fmaf(tanh_fast(m1 - m2v[pi][i]), vmv[i], am);
                    ab = fmaf(hpv[pi][i], g, ab);
                }
                #pragma unroll
                for (int o = 16; o; o >>= 1) {
                    ac += __shfl_xor_sync(0xffffffffu, ac, o);
                    am += __shfl_xor_sync(0xffffffffu, am, o);
                    ab += __shfl_xor_sync(0xffffffffu, ab, o);
                }
                if (lane == 0) {
                    int p = p0 + w + 8 * pi;
                    int q = q0 + c * 8 + r;
                    int idx = (b * LL + p) * LL + q;
                    g_SC[idx] = ac;
                    g_SB[idx] = ab;
                    g_SM[idx] = am;
                }
            }
        }
        __syncthreads();
    }
}

// ======================= kernel 4 (F2): softmax + attend, all 4 branches =======================
__global__ __launch_bounds__(256)
void attend_kernel(const float* __restrict__ Hq, float* __restrict__ out) {
    __shared__ float wsm[256][36];   // [q][slot=p*4+br], padded

    const int p0 = blockIdx.x * 8, b = blockIdx.y;
    const int tid = threadIdx.x, lane = tid & 31, w = tid >> 5;

    const float* srcs[4] = {g_SC, g_SB, g_SD, g_SM};
    #pragma unroll
    for (int t = 0; t < 32; ++t) {
        int i = tid + t * 256;          // 0..8191: (p, br, q)
        int p = i >> 10, br = (i >> 8) & 3, q = i & 255;
        wsm[q][p * 4 + br] = srcs[br][(b * LL + p0 + p) * LL + q];
    }
    __syncthreads();

    #pragma unroll
    for (int s = 0; s < 4; ++s) {
        int slot = w + 8 * s;
        float v[8];
        #pragma unroll
        for (int i = 0; i < 8; ++i) v[i] = wsm[lane + 32 * i][slot];
        float mx = v[0];
        #pragma unroll
        for (int i = 1; i < 8; ++i) mx = fmaxf(mx, v[i]);
        #pragma unroll
        for (int o = 16; o; o >>= 1) mx = fmaxf(mx, __shfl_xor_sync(0xffffffffu, mx, o));
        float sum = 0.f;
        #pragma unroll
        for (int i = 0; i < 8; ++i) { v[i] = __expf(v[i] - mx); sum += v[i]; }
        #pragma unroll
        for (int o = 16; o; o >>= 1) sum += __shfl_xor_sync(0xffffffffu, sum, o);
        float inv = 1.0f / sum;
        #pragma unroll
        for (int i = 0; i < 8; ++i) wsm[lane + 32 * i][slot] = v[i] * inv;
    }
    __syncthreads();

    float acc[32];
    #pragma unroll
    for (int s = 0; s < 32; ++s) acc[s] = 0.f;
    const float* hqb = &Hq[(b * LL) * DD + tid];
    #pragma unroll 4
    for (int q = 0; q < LL; ++q) {
        float hq = hqb[q * DD];
        #pragma unroll
        for (int j = 0; j < 8; ++j) {
            float4 wv = *reinterpret_cast<const float4*>(&wsm[q][j * 4]);
            acc[j * 4 + 0] = fmaf(wv.x, hq, acc[j * 4 + 0]);
            acc[j * 4 + 1] = fmaf(wv.y, hq, acc[j * 4 + 1]);
            acc[j * 4 + 2] = fmaf(wv.z, hq, acc[j * 4 + 2]);
            acc[j * 4 + 3] = fmaf(wv.w, hq, acc[j * 4 + 3]);
        }
    }
    const int BR = BB * LL * DD;
    #pragma unroll
    for (int p = 0; p < 8; ++p)
        #pragma unroll
        for (int br = 0; br < 4; ++br)
            out[br * BR + (b * LL + p0 + p) * DD + tid] = acc[p * 4 + br];
}

// ======================= launch =======================
extern "C" void kernel_launch(void* const* d_in, const int* in_sizes, int n_in,
                              void* d_out, int out_size) {
    (void)in_sizes; (void)n_in; (void)out_size;
    const float* Hp  = (const float*)d_in[0];
    const float* Hq  = (const float*)d_in[1];
    const float* Wc1 = (const float*)d_in[2];
    const float* Wc2 = (const float*)d_in[3];
    const float* vc  = (const float*)d_in[4];
    const float* Wb  = (const float*)d_in[5];
    const float* Wd  = (const float*)d_in[6];
    const float* vd  = (const float*)d_in[7];
    const float* Wm  = (const float*)d_in[8];
    const float* vm  = (const float*)d_in[9];
    float* out = (float*)d_out;

    cudaFuncSetAttribute(branchd_kernel,
                         cudaFuncAttributeMaxDynamicSharedMemorySize, SMEM_D);

    prep_wd_kernel<<<DD, HH>>>(Wd);

    dim3 gproj(16, 4, 5);
    proj_kernel<<<gproj, 256>>>(Hp, Hq, Wc1, Wc2, Wb, Wm);

    dim3 gd(LL, BB);
    branchd_kernel<<<gd, 256, SMEM_D>>>(Hp, Hq, vd);

    dim3 gs(4, 16, 4);
    score_kernel<<<gs, 256>>>(Hp, vc, vm);

    dim3 ga(32, 4);
    attend_kernel<<<ga, 256>>>(Hq, out);
}